// round 13
// baseline (speedup 1.0000x reference)
#include <cuda_runtime.h>
#include <math.h>
#include <stdint.h>

#define G 4096
#define D 128

#define NEG_BIG (-3.402823466e+38f)
#define LOG2E 1.44269504088896340736f

// ---------- static device scratch ----------
__device__ uint2 g_Wsp[256 * 512];   // combined weight, tf32 hi/lo split, [k][n'], n' = d*4+gate
__device__ float g_bias[512];        // permuted bias
__device__ float g_h[G * D];
__device__ float g_c[G * D];
__device__ float g_r[G * D];
__device__ float g_h1[D];
__device__ float g_c1[D];
__device__ float g_g1base[512];      // permuted
__device__ int   g_segofs[G + 1];

__device__ __forceinline__ float sigf(float x) { return 1.f / (1.f + __expf(-x)); }

__device__ __forceinline__ float ex2(float x) {
    float r;
    asm("ex2.approx.ftz.f32 %0, %1;" : "=f"(r) : "f"(x));
    return r;
}

__device__ __forceinline__ uint32_t f2tf32(float v) {
    uint32_t r;
    asm("cvt.rna.tf32.f32 %0, %1;" : "=r"(r) : "f"(v));
    return r;
}

__device__ __forceinline__ void mma_tf32(float4& d, uint32_t a0, uint32_t a1, uint32_t a2,
                                         uint32_t a3, uint32_t b0, uint32_t b1) {
    asm volatile(
        "mma.sync.aligned.m16n8k8.row.col.f32.tf32.tf32.f32 "
        "{%0,%1,%2,%3}, {%4,%5,%6,%7}, {%8,%9}, {%0,%1,%2,%3};"
        : "+f"(d.x), "+f"(d.y), "+f"(d.z), "+f"(d.w)
        : "r"(a0), "r"(a1), "r"(a2), "r"(a3), "r"(b0), "r"(b1));
}

__device__ __forceinline__ uint2 split_tf32(float v) {
    uint32_t hi = f2tf32(v);
    float lo = v - __uint_as_float(hi);
    uint2 r; r.x = hi; r.y = f2tf32(lo);
    return r;
}

// ---------- setup: weight permute+split + bias + segment bounds, one launch ----------
__global__ void prep_all(const float* __restrict__ W_ih, const float* __restrict__ W_hh,
                         const float* __restrict__ b_ih, const float* __restrict__ b_hh,
                         const int* __restrict__ idx32, int N) {
    int bid = blockIdx.x;
    int t = threadIdx.x;
    if (bid < 512) {
        int idx = bid * 256 + t;
        int n = idx >> 8, k = idx & 255;
        int gate = n >> 7, d = n & 127;
        float w = W_ih[n * 256 + k];
        if (k < 128) w += W_hh[n * 128 + k];
        g_Wsp[k * 512 + d * 4 + gate] = split_tf32(w);
    } else {
        int gidx = (bid - 512) * 256 + t;
        if (gidx < 512) {
            int gate = gidx >> 7, d = gidx & 127;
            g_bias[d * 4 + gate] = b_ih[gidx] + b_hh[gidx];
        }
        if (gidx <= G) {
            int j = ((N - 1) & 1) ? (N - 1) : (N - 2);
            bool is64 = (idx32[j] == 0);
            const long long* idx64 = (const long long*)idx32;
            int lo = 0, hi = N;
            while (lo < hi) {
                int mid = (lo + hi) >> 1;
                long long v = is64 ? idx64[mid] : (long long)idx32[mid];
                if (v < (long long)gidx) lo = mid + 1; else hi = mid;
            }
            g_segofs[gidx] = lo;
        }
    }
}

// Fused: step-1 closed-form LSTM (state 0) + g1base (rank-1 part of step 2's gates).
__global__ void prep_state() {
    __shared__ float sh1[128];
    int t = threadIdx.x;
    if (t < 128) {
        float i = g_bias[t * 4 + 0], gg = g_bias[t * 4 + 2], o = g_bias[t * 4 + 3];
        float c = sigf(i) * tanhf(gg);
        float h = sigf(o) * tanhf(c);
        g_c1[t] = c;
        g_h1[t] = h;
        sh1[t] = h;
    }
    __syncthreads();
    float acc = g_bias[t];
    #pragma unroll 8
    for (int k = 0; k < 128; k++) {
        uint2 w = g_Wsp[k * 512 + t];
        acc += sh1[k] * (__uint_as_float(w.x) + __uint_as_float(w.y));
    }
    g_g1base[t] = acc;
}

// ---------- tensor-core GEMM (tf32 hi/lo split = fp32-accurate) + fused LSTM cell ----------
// gates[m][n'] = base[n'] + (HAS_A1 ? h@W[0:128] : 0) + r@W[128:256]; cell in epilogue.
// Block tile 128x128, grid (32,4)=128 blocks (one wave), 8 warps (warp tile 32x64),
// BK=32, single smem buffer + register prefetch. Fragments: m16n8k8 tf32, 3-mma split.
#define AS_STRIDE 36
#define BS_STRIDE 132
#define AS_ELEMS (128 * AS_STRIDE)
#define GEMM_SMEM_BYTES ((AS_ELEMS + 32 * BS_STRIDE) * 8)

template <bool HAS_A1, bool CVEC>
__global__ void __launch_bounds__(256) gemm_lstm_mma() {
    extern __shared__ uint2 smem_dyn[];
    uint2* As = smem_dyn;                 // [m][k] m<128, k<32, stride 36
    uint2* Bs = smem_dyn + AS_ELEMS;      // [k][n] k<32, n<128, stride 132

    const int bx = blockIdx.x;            // m tile (0..31)
    const int by = blockIdx.y;            // n tile (0..3)
    const int t = threadIdx.x;
    const int wid = t >> 5, l = t & 31;
    const int wm = wid >> 1, wn = wid & 1;          // warp grid 4x2
    const int r = l >> 2, c = l & 3;

    const int m0 = bx * 128;
    const int n0 = by * 128;

    const int NCHUNK = HAS_A1 ? 8 : 4;
    const int KB0 = HAS_A1 ? 0 : 128;

    // staging thread coords
    const int a_row = t >> 3;             // + i*32
    const int a_kq = (t & 7) * 4;
    const int b_k = t >> 5;               // + i*8
    const int b_nq = (t & 31) * 4;

    float4 acc[2][8];
    #pragma unroll
    for (int mi = 0; mi < 2; mi++)
        #pragma unroll
        for (int ni = 0; ni < 8; ni++) acc[mi][ni] = make_float4(0.f, 0.f, 0.f, 0.f);

    float4 a_st[4];
    uint4 b_st[4][2];

    // load chunk 0
    {
        int kb = KB0;
        const float* A = (kb < 128) ? g_h : g_r;
        int kl = kb & 127;
        #pragma unroll
        for (int i = 0; i < 4; i++)
            a_st[i] = *(const float4*)&A[(size_t)(m0 + a_row + i * 32) * 128 + kl + a_kq];
        #pragma unroll
        for (int i = 0; i < 4; i++) {
            const uint2* src = &g_Wsp[(size_t)(kb + b_k + i * 8) * 512 + n0 + b_nq];
            b_st[i][0] = *(const uint4*)&src[0];
            b_st[i][1] = *(const uint4*)&src[2];
        }
    }
    #pragma unroll
    for (int i = 0; i < 4; i++) {
        uint2* d = &As[(a_row + i * 32) * AS_STRIDE + a_kq];
        d[0] = split_tf32(a_st[i].x); d[1] = split_tf32(a_st[i].y);
        d[2] = split_tf32(a_st[i].z); d[3] = split_tf32(a_st[i].w);
        uint2* e = &Bs[(b_k + i * 8) * BS_STRIDE + b_nq];
        *(uint4*)&e[0] = b_st[i][0];
        *(uint4*)&e[2] = b_st[i][1];
    }
    __syncthreads();

    for (int chunk = 0; chunk < NCHUNK; chunk++) {
        if (chunk + 1 < NCHUNK) {
            int kb = KB0 + (chunk + 1) * 32;
            const float* A = (kb < 128) ? g_h : g_r;
            int kl = kb & 127;
            #pragma unroll
            for (int i = 0; i < 4; i++)
                a_st[i] = *(const float4*)&A[(size_t)(m0 + a_row + i * 32) * 128 + kl + a_kq];
            #pragma unroll
            for (int i = 0; i < 4; i++) {
                const uint2* src = &g_Wsp[(size_t)(kb + b_k + i * 8) * 512 + n0 + b_nq];
                b_st[i][0] = *(const uint4*)&src[0];
                b_st[i][1] = *(const uint4*)&src[2];
            }
        }

        #pragma unroll
        for (int ks = 0; ks < 4; ks++) {
            int k0 = ks * 8;
            uint2 af[2][4];
            #pragma unroll
            for (int mi = 0; mi < 2; mi++) {
                int mb = wm * 32 + mi * 16;
                af[mi][0] = As[(mb + r) * AS_STRIDE + k0 + c];
                af[mi][1] = As[(mb + r + 8) * AS_STRIDE + k0 + c];
                af[mi][2] = As[(mb + r) * AS_STRIDE + k0 + c + 4];
                af[mi][3] = As[(mb + r + 8) * AS_STRIDE + k0 + c + 4];
            }
            uint2 bf[8][2];
            #pragma unroll
            for (int ni = 0; ni < 8; ni++) {
                int nb = wn * 64 + ni * 8;
                bf[ni][0] = Bs[(k0 + c) * BS_STRIDE + nb + r];
                bf[ni][1] = Bs[(k0 + c + 4) * BS_STRIDE + nb + r];
            }
            #pragma unroll
            for (int mi = 0; mi < 2; mi++) {
                #pragma unroll
                for (int ni = 0; ni < 8; ni++) {
                    // hi*hi
                    mma_tf32(acc[mi][ni], af[mi][0].x, af[mi][1].x, af[mi][2].x, af[mi][3].x,
                             bf[ni][0].x, bf[ni][1].x);
                    // hi*lo
                    mma_tf32(acc[mi][ni], af[mi][0].x, af[mi][1].x, af[mi][2].x, af[mi][3].x,
                             bf[ni][0].y, bf[ni][1].y);
                    // lo*hi
                    mma_tf32(acc[mi][ni], af[mi][0].y, af[mi][1].y, af[mi][2].y, af[mi][3].y,
                             bf[ni][0].x, bf[ni][1].x);
                }
            }
        }
        __syncthreads();
        if (chunk + 1 < NCHUNK) {
            #pragma unroll
            for (int i = 0; i < 4; i++) {
                uint2* d = &As[(a_row + i * 32) * AS_STRIDE + a_kq];
                d[0] = split_tf32(a_st[i].x); d[1] = split_tf32(a_st[i].y);
                d[2] = split_tf32(a_st[i].z); d[3] = split_tf32(a_st[i].w);
                uint2* e = &Bs[(b_k + i * 8) * BS_STRIDE + b_nq];
                *(uint4*)&e[0] = b_st[i][0];
                *(uint4*)&e[2] = b_st[i][1];
            }
            __syncthreads();
        }
    }

    // ---- fused LSTM epilogue (validated in R5) ----
    // acc[mi][ni]: (.x,.y)=(row mg, n'=np,np+1), (.z,.w)=(row mg+8, same n'), np=nb+2c.
    // Gate quad of d lives in lane pair (c even: i,f; c odd: g,o). shfl_xor(1) redistributes:
    // even lane computes row mg's cell; odd lane computes row mg+8's cell.
    const float* base = CVEC ? g_g1base : g_bias;
    const bool even = (c & 1) == 0;
    #pragma unroll
    for (int mi = 0; mi < 2; mi++) {
        int mg = m0 + wm * 32 + mi * 16 + r;
        #pragma unroll
        for (int ni = 0; ni < 8; ni++) {
            int nb = n0 + wn * 64 + ni * 8;
            int d = (nb >> 2) + (c >> 1);
            float4 v = acc[mi][ni];
            float ox = __shfl_xor_sync(0xffffffffu, v.x, 1);
            float oy = __shfl_xor_sync(0xffffffffu, v.y, 1);
            float oz = __shfl_xor_sync(0xffffffffu, v.z, 1);
            float ow = __shfl_xor_sync(0xffffffffu, v.w, 1);
            float4 bz = *(const float4*)&base[d * 4];
            float gi, gf, gg, go;
            int row;
            if (even) { gi = v.x; gf = v.y; gg = ox; go = oy; row = mg; }
            else      { gi = oz; gf = ow; gg = v.z; go = v.w; row = mg + 8; }
            gi += bz.x; gf += bz.y; gg += bz.z; go += bz.w;
            float cold = CVEC ? g_c1[d] : g_c[(size_t)row * 128 + d];
            float cn = sigf(gf) * cold + sigf(gi) * tanhf(gg);
            g_c[(size_t)row * 128 + d] = cn;
            g_h[(size_t)row * 128 + d] = sigf(go) * tanhf(cn);
        }
    }
}

// ---------- attention: per-segment online softmax, single pass over x ----------
template <bool QBCAST, bool FINAL>
__global__ void __launch_bounds__(128) attn_kernel(const float* __restrict__ x,
                                                   float* __restrict__ out) {
    int g = blockIdx.x;
    int start = g_segofs[g], end = g_segofs[g + 1];
    int t = threadIdx.x, w = t >> 5, l = t & 31;
    int i8 = l & 7, grp = l >> 3;
    const float* qrow = QBCAST ? g_h1 : (g_h + (size_t)g * D);

    float4 qv[4];
    #pragma unroll
    for (int j = 0; j < 4; j++) {
        float4 q = *(const float4*)&qrow[i8 * 4 + 32 * j];
        qv[j].x = q.x * LOG2E; qv[j].y = q.y * LOG2E;
        qv[j].z = q.z * LOG2E; qv[j].w = q.w * LOG2E;
    }

    float m = NEG_BIG, s = 0.f;
    float4 acc[4] = {};

    for (int r0 = start + w * 8; r0 < end; r0 += 32) {
        int ra = r0 + grp, rb = r0 + 4 + grp;
        bool va = ra < end, vb = rb < end;
        int rac = va ? ra : end - 1;
        int rbc = vb ? rb : end - 1;
        const float* xra = x + (size_t)rac * D + i8 * 4;
        const float* xrb = x + (size_t)rbc * D + i8 * 4;
        float4 xa[4], xb[4];
        #pragma unroll
        for (int j = 0; j < 4; j++) xa[j] = *(const float4*)&xra[32 * j];
        #pragma unroll
        for (int j = 0; j < 4; j++) xb[j] = *(const float4*)&xrb[32 * j];

        float ea = xa[0].x * qv[0].x + xa[0].y * qv[0].y + xa[0].z * qv[0].z + xa[0].w * qv[0].w;
        float eb = xb[0].x * qv[0].x + xb[0].y * qv[0].y + xb[0].z * qv[0].z + xb[0].w * qv[0].w;
        #pragma unroll
        for (int j = 1; j < 4; j++) {
            ea += xa[j].x * qv[j].x + xa[j].y * qv[j].y + xa[j].z * qv[j].z + xa[j].w * qv[j].w;
            eb += xb[j].x * qv[j].x + xb[j].y * qv[j].y + xb[j].z * qv[j].z + xb[j].w * qv[j].w;
        }
        ea += __shfl_xor_sync(0xffffffffu, ea, 1);
        eb += __shfl_xor_sync(0xffffffffu, eb, 1);
        ea += __shfl_xor_sync(0xffffffffu, ea, 2);
        eb += __shfl_xor_sync(0xffffffffu, eb, 2);
        ea += __shfl_xor_sync(0xffffffffu, ea, 4);
        eb += __shfl_xor_sync(0xffffffffu, eb, 4);

        float eva = va ? ea : NEG_BIG;
        float evb = vb ? eb : NEG_BIG;
        float mn = fmaxf(m, fmaxf(eva, evb));
        float sc = ex2(m - mn);
        float pa = ex2(eva - mn);
        float pb = ex2(evb - mn);
        pa = va ? pa : 0.f;
        pb = vb ? pb : 0.f;
        s = s * sc + pa + pb;
        #pragma unroll
        for (int j = 0; j < 4; j++) {
            acc[j].x = acc[j].x * sc + pa * xa[j].x + pb * xb[j].x;
            acc[j].y = acc[j].y * sc + pa * xa[j].y + pb * xb[j].y;
            acc[j].z = acc[j].z * sc + pa * xa[j].z + pb * xb[j].z;
            acc[j].w = acc[j].w * sc + pa * xa[j].w + pb * xb[j].w;
        }
        m = mn;
    }

    #pragma unroll
    for (int ofs = 8; ofs <= 16; ofs <<= 1) {
        float m2 = __shfl_xor_sync(0xffffffffu, m, ofs);
        float s2 = __shfl_xor_sync(0xffffffffu, s, ofs);
        float M2 = fmaxf(m, m2);
        float fa = ex2(m - M2), fb = ex2(m2 - M2);
        s = s * fa + s2 * fb;
        #pragma unroll
        for (int j = 0; j < 4; j++) {
            float ox = __shfl_xor_sync(0xffffffffu, acc[j].x, ofs);
            float oy = __shfl_xor_sync(0xffffffffu, acc[j].y, ofs);
            float oz = __shfl_xor_sync(0xffffffffu, acc[j].z, ofs);
            float ow = __shfl_xor_sync(0xffffffffu, acc[j].w, ofs);
            acc[j].x = acc[j].x * fa + ox * fb;
            acc[j].y = acc[j].y * fa + oy * fb;
            acc[j].z = acc[j].z * fa + oz * fb;
            acc[j].w = acc[j].w * fa + ow * fb;
        }
        m = M2;
    }

    __shared__ float sm_m[4], sm_s[4];
    __shared__ float sm_acc[4][128];
    if (l < 8) {
        #pragma unroll
        for (int j = 0; j < 4; j++) *(float4*)&sm_acc[w][i8 * 4 + 32 * j] = acc[j];
        if (l == 0) { sm_m[w] = m; sm_s[w] = s; }
    }
    __syncthreads();

    float M = fmaxf(fmaxf(sm_m[0], sm_m[1]), fmaxf(sm_m[2], sm_m[3]));
    float stot = 0.f, racc = 0.f;
    #pragma unroll
    for (int ww = 0; ww < 4; ww++) {
        float fsc = ex2(sm_m[ww] - M);
        stot += fsc * sm_s[ww];
        racc += fsc * sm_acc[ww][t];
    }
    float r = racc / fmaxf(stot, 1e-16f);
    if (FINAL) {
        out[(size_t)g * 256 + 128 + t] = r;
        out[(size_t)g * 256 + t] = qrow[t];
    } else {
        g_r[(size_t)g * D + t] = r;
    }
}

// ---------- launch ----------
extern "C" void kernel_launch(void* const* d_in, const int* in_sizes, int n_in,
                              void* d_out, int out_size) {
    const float* x    = (const float*)d_in[0];
    const float* W_ih = (const float*)d_in[1];
    const float* W_hh = (const float*)d_in[2];
    const float* b_ih = (const float*)d_in[3];
    const float* b_hh = (const float*)d_in[4];
    const int*   idx  = (const int*)d_in[5];
    float* out = (float*)d_out;
    int N = in_sizes[5];
    (void)n_in; (void)out_size;

    cudaFuncSetAttribute(gemm_lstm_mma<false, true>,
                         cudaFuncAttributeMaxDynamicSharedMemorySize, GEMM_SMEM_BYTES);
    cudaFuncSetAttribute(gemm_lstm_mma<true, false>,
                         cudaFuncAttributeMaxDynamicSharedMemorySize, GEMM_SMEM_BYTES);

    // 1: setup (weight permute+split + bias + segment bounds)
    prep_all<<<512 + 17, 256>>>(W_ih, W_hh, b_ih, b_hh, idx, N);
    // 2: step-1 LSTM closed form + rank-1 gate base for step 2
    prep_state<<<1, 512>>>();
    // 3: step 1 attention (q = h1 broadcast) -> r1
    attn_kernel<true, false><<<G, 128>>>(x, out);
    // 4: step 2 gates + LSTM fused -> h2, c2
    gemm_lstm_mma<false, true><<<dim3(32, 4), 256, GEMM_SMEM_BYTES>>>();
    // 5: step 2 attention -> r2
    attn_kernel<false, false><<<G, 128>>>(x, out);
    // 6: step 3 gates + LSTM fused -> h3, c3
    gemm_lstm_mma<true, false><<<dim3(32, 4), 256, GEMM_SMEM_BYTES>>>();
    // 7: step 3 attention -> q_star
    attn_kernel<false, true><<<G, 128>>>(x, out);
}

// round 14
// speedup vs baseline: 1.0032x; 1.0032x over previous
#include <cuda_runtime.h>
#include <math.h>
#include <stdint.h>

#define G 4096
#define D 128

#define NEG_BIG (-3.402823466e+38f)
#define LOG2E 1.44269504088896340736f

// ---------- static device scratch ----------
__device__ uint2 g_Wsp[256 * 512];   // combined weight, tf32 hi/lo split, [k][n'], n' = d*4+gate
__device__ float g_bias[512];        // permuted bias
__device__ float g_h[G * D];
__device__ float g_c[G * D];
__device__ float g_r[G * D];
__device__ float g_gates[G * 512];   // raw GEMM output (no bias), permuted n'
__device__ float g_h1[D];
__device__ float g_c1[D];
__device__ float g_g1base[512];      // permuted
__device__ int   g_segofs[G + 1];

__device__ __forceinline__ float sigf(float x) { return 1.f / (1.f + __expf(-x)); }

__device__ __forceinline__ float ex2(float x) {
    float r;
    asm("ex2.approx.ftz.f32 %0, %1;" : "=f"(r) : "f"(x));
    return r;
}

__device__ __forceinline__ uint32_t f2tf32(float v) {
    uint32_t r;
    asm("cvt.rna.tf32.f32 %0, %1;" : "=r"(r) : "f"(v));
    return r;
}

__device__ __forceinline__ void mma_tf32(float4& d, uint32_t a0, uint32_t a1, uint32_t a2,
                                         uint32_t a3, uint32_t b0, uint32_t b1) {
    asm volatile(
        "mma.sync.aligned.m16n8k8.row.col.f32.tf32.tf32.f32 "
        "{%0,%1,%2,%3}, {%4,%5,%6,%7}, {%8,%9}, {%0,%1,%2,%3};"
        : "+f"(d.x), "+f"(d.y), "+f"(d.z), "+f"(d.w)
        : "r"(a0), "r"(a1), "r"(a2), "r"(a3), "r"(b0), "r"(b1));
}

__device__ __forceinline__ uint2 split_tf32(float v) {
    uint32_t hi = f2tf32(v);
    float lo = v - __uint_as_float(hi);
    uint2 r; r.x = hi; r.y = f2tf32(lo);
    return r;
}

// ---------- setup: weight permute+split + bias + segment bounds, one launch ----------
__global__ void prep_all(const float* __restrict__ W_ih, const float* __restrict__ W_hh,
                         const float* __restrict__ b_ih, const float* __restrict__ b_hh,
                         const int* __restrict__ idx32, int N) {
    int bid = blockIdx.x;
    int t = threadIdx.x;
    if (bid < 512) {
        int idx = bid * 256 + t;
        int n = idx >> 8, k = idx & 255;
        int gate = n >> 7, d = n & 127;
        float w = W_ih[n * 256 + k];
        if (k < 128) w += W_hh[n * 128 + k];
        g_Wsp[k * 512 + d * 4 + gate] = split_tf32(w);
    } else {
        int gidx = (bid - 512) * 256 + t;
        if (gidx < 512) {
            int gate = gidx >> 7, d = gidx & 127;
            g_bias[d * 4 + gate] = b_ih[gidx] + b_hh[gidx];
        }
        if (gidx <= G) {
            int j = ((N - 1) & 1) ? (N - 1) : (N - 2);
            bool is64 = (idx32[j] == 0);
            const long long* idx64 = (const long long*)idx32;
            int lo = 0, hi = N;
            while (lo < hi) {
                int mid = (lo + hi) >> 1;
                long long v = is64 ? idx64[mid] : (long long)idx32[mid];
                if (v < (long long)gidx) lo = mid + 1; else hi = mid;
            }
            g_segofs[gidx] = lo;
        }
    }
}

// Fused: step-1 closed-form LSTM (state 0) + g1base (rank-1 part of step 2's gates).
__global__ void prep_state() {
    __shared__ float sh1[128];
    int t = threadIdx.x;
    if (t < 128) {
        float i = g_bias[t * 4 + 0], gg = g_bias[t * 4 + 2], o = g_bias[t * 4 + 3];
        float c = sigf(i) * tanhf(gg);
        float h = sigf(o) * tanhf(c);
        g_c1[t] = c;
        g_h1[t] = h;
        sh1[t] = h;
    }
    __syncthreads();
    float acc = g_bias[t];
    #pragma unroll 8
    for (int k = 0; k < 128; k++) {
        uint2 w = g_Wsp[k * 512 + t];
        acc += sh1[k] * (__uint_as_float(w.x) + __uint_as_float(w.y));
    }
    g_g1base[t] = acc;
}

// ---------- tensor-core GEMM (tf32 hi/lo split = fp32-accurate) ----------
// gates_raw[m][n'] = (HAS_A1 ? h@W[0:128] : 0) + r@W[128:256]  (bias added in lstm_elem)
// Block tile 128x128, grid (32,4)=128 blocks (one wave), 512 threads = 16 warps
// (4m x 4n, warp tile 32x32), BK=32, single smem buffer + register prefetch.
#define AS_STRIDE 36
#define BS_STRIDE 132
#define AS_ELEMS (128 * AS_STRIDE)
#define GEMM_SMEM_BYTES ((AS_ELEMS + 32 * BS_STRIDE) * 8)

template <bool HAS_A1>
__global__ void __launch_bounds__(512) gemm_mma() {
    extern __shared__ uint2 smem_dyn[];
    uint2* As = smem_dyn;                 // [m][k] m<128, k<32, stride 36
    uint2* Bs = smem_dyn + AS_ELEMS;      // [k][n] k<32, n<128, stride 132

    const int bx = blockIdx.x;            // m tile (0..31)
    const int by = blockIdx.y;            // n tile (0..3)
    const int t = threadIdx.x;
    const int wid = t >> 5, l = t & 31;
    const int wm = wid >> 2, wn = wid & 3;          // warp grid 4x4
    const int r = l >> 2, c = l & 3;

    const int m0 = bx * 128;
    const int n0 = by * 128;

    const int NCHUNK = HAS_A1 ? 8 : 4;
    const int KB0 = HAS_A1 ? 0 : 128;

    // staging thread coords (512 threads)
    const int a_row = t >> 2;             // 0..127
    const int a_kq = (t & 3) * 8;         // 0,8,16,24
    const int b_k = t >> 4;               // 0..31
    const int b_nq = (t & 15) * 8;        // 0..120 (8 uint2 each)

    float4 acc[2][4];
    #pragma unroll
    for (int mi = 0; mi < 2; mi++)
        #pragma unroll
        for (int ni = 0; ni < 4; ni++) acc[mi][ni] = make_float4(0.f, 0.f, 0.f, 0.f);

    float4 a_st[2];
    uint4 b_st[4];

    // load chunk 0
    {
        int kb = KB0;
        const float* A = (kb < 128) ? g_h : g_r;
        int kl = kb & 127;
        a_st[0] = *(const float4*)&A[(size_t)(m0 + a_row) * 128 + kl + a_kq];
        a_st[1] = *(const float4*)&A[(size_t)(m0 + a_row) * 128 + kl + a_kq + 4];
        const uint2* src = &g_Wsp[(size_t)(kb + b_k) * 512 + n0 + b_nq];
        #pragma unroll
        for (int i = 0; i < 4; i++) b_st[i] = *(const uint4*)&src[2 * i];
    }
    {
        uint2* d = &As[a_row * AS_STRIDE + a_kq];
        d[0] = split_tf32(a_st[0].x); d[1] = split_tf32(a_st[0].y);
        d[2] = split_tf32(a_st[0].z); d[3] = split_tf32(a_st[0].w);
        d[4] = split_tf32(a_st[1].x); d[5] = split_tf32(a_st[1].y);
        d[6] = split_tf32(a_st[1].z); d[7] = split_tf32(a_st[1].w);
        uint2* e = &Bs[b_k * BS_STRIDE + b_nq];
        #pragma unroll
        for (int i = 0; i < 4; i++) *(uint4*)&e[2 * i] = b_st[i];
    }
    __syncthreads();

    for (int chunk = 0; chunk < NCHUNK; chunk++) {
        if (chunk + 1 < NCHUNK) {
            int kb = KB0 + (chunk + 1) * 32;
            const float* A = (kb < 128) ? g_h : g_r;
            int kl = kb & 127;
            a_st[0] = *(const float4*)&A[(size_t)(m0 + a_row) * 128 + kl + a_kq];
            a_st[1] = *(const float4*)&A[(size_t)(m0 + a_row) * 128 + kl + a_kq + 4];
            const uint2* src = &g_Wsp[(size_t)(kb + b_k) * 512 + n0 + b_nq];
            #pragma unroll
            for (int i = 0; i < 4; i++) b_st[i] = *(const uint4*)&src[2 * i];
        }

        #pragma unroll
        for (int ks = 0; ks < 4; ks++) {
            int k0 = ks * 8;
            uint2 af[2][4];
            #pragma unroll
            for (int mi = 0; mi < 2; mi++) {
                int mb = wm * 32 + mi * 16;
                af[mi][0] = As[(mb + r) * AS_STRIDE + k0 + c];
                af[mi][1] = As[(mb + r + 8) * AS_STRIDE + k0 + c];
                af[mi][2] = As[(mb + r) * AS_STRIDE + k0 + c + 4];
                af[mi][3] = As[(mb + r + 8) * AS_STRIDE + k0 + c + 4];
            }
            uint2 bf[4][2];
            #pragma unroll
            for (int ni = 0; ni < 4; ni++) {
                int nb = wn * 32 + ni * 8;
                bf[ni][0] = Bs[(k0 + c) * BS_STRIDE + nb + r];
                bf[ni][1] = Bs[(k0 + c + 4) * BS_STRIDE + nb + r];
            }
            #pragma unroll
            for (int mi = 0; mi < 2; mi++) {
                #pragma unroll
                for (int ni = 0; ni < 4; ni++) {
                    // hi*hi
                    mma_tf32(acc[mi][ni], af[mi][0].x, af[mi][1].x, af[mi][2].x, af[mi][3].x,
                             bf[ni][0].x, bf[ni][1].x);
                    // hi*lo
                    mma_tf32(acc[mi][ni], af[mi][0].x, af[mi][1].x, af[mi][2].x, af[mi][3].x,
                             bf[ni][0].y, bf[ni][1].y);
                    // lo*hi
                    mma_tf32(acc[mi][ni], af[mi][0].y, af[mi][1].y, af[mi][2].y, af[mi][3].y,
                             bf[ni][0].x, bf[ni][1].x);
                }
            }
        }
        __syncthreads();
        if (chunk + 1 < NCHUNK) {
            uint2* d = &As[a_row * AS_STRIDE + a_kq];
            d[0] = split_tf32(a_st[0].x); d[1] = split_tf32(a_st[0].y);
            d[2] = split_tf32(a_st[0].z); d[3] = split_tf32(a_st[0].w);
            d[4] = split_tf32(a_st[1].x); d[5] = split_tf32(a_st[1].y);
            d[6] = split_tf32(a_st[1].z); d[7] = split_tf32(a_st[1].w);
            uint2* e = &Bs[b_k * BS_STRIDE + b_nq];
            #pragma unroll
            for (int i = 0; i < 4; i++) *(uint4*)&e[2 * i] = b_st[i];
            __syncthreads();
        }
    }

    // store raw gates
    #pragma unroll
    for (int mi = 0; mi < 2; mi++) {
        int mg = m0 + wm * 32 + mi * 16 + r;
        #pragma unroll
        for (int ni = 0; ni < 4; ni++) {
            int np = n0 + wn * 32 + ni * 8 + 2 * c;
            float2 loa; loa.x = acc[mi][ni].x; loa.y = acc[mi][ni].y;
            float2 hib; hib.x = acc[mi][ni].z; hib.y = acc[mi][ni].w;
            *(float2*)&g_gates[(size_t)mg * 512 + np] = loa;
            *(float2*)&g_gates[(size_t)(mg + 8) * 512 + np] = hib;
        }
    }
}

// ---------- LSTM elementwise: bias add + cell ----------
template <bool CVEC, bool G1BASE>
__global__ void lstm_elem() {
    int idx = blockIdx.x * blockDim.x + threadIdx.x;
    if (idx >= G * D) return;
    int m = idx >> 7, d = idx & 127;
    float4 gv = *(const float4*)&g_gates[(size_t)m * 512 + d * 4];
    const float* base = G1BASE ? g_g1base : g_bias;
    float4 bz = *(const float4*)&base[d * 4];
    float gi = gv.x + bz.x, gf = gv.y + bz.y, gg = gv.z + bz.z, go = gv.w + bz.w;
    float cold = CVEC ? g_c1[d] : g_c[idx];
    float cc = sigf(gf) * cold + sigf(gi) * tanhf(gg);
    g_c[idx] = cc;
    g_h[idx] = sigf(go) * tanhf(cc);
}

// ---------- attention: per-segment online softmax, single pass over x ----------
template <bool QBCAST, bool FINAL>
__global__ void __launch_bounds__(128) attn_kernel(const float* __restrict__ x,
                                                   float* __restrict__ out) {
    int g = blockIdx.x;
    int start = g_segofs[g], end = g_segofs[g + 1];
    int t = threadIdx.x, w = t >> 5, l = t & 31;
    int i8 = l & 7, grp = l >> 3;
    const float* qrow = QBCAST ? g_h1 : (g_h + (size_t)g * D);

    float4 qv[4];
    #pragma unroll
    for (int j = 0; j < 4; j++) {
        float4 q = *(const float4*)&qrow[i8 * 4 + 32 * j];
        qv[j].x = q.x * LOG2E; qv[j].y = q.y * LOG2E;
        qv[j].z = q.z * LOG2E; qv[j].w = q.w * LOG2E;
    }

    float m = NEG_BIG, s = 0.f;
    float4 acc[4] = {};

    for (int r0 = start + w * 8; r0 < end; r0 += 32) {
        int ra = r0 + grp, rb = r0 + 4 + grp;
        bool va = ra < end, vb = rb < end;
        int rac = va ? ra : end - 1;
        int rbc = vb ? rb : end - 1;
        const float* xra = x + (size_t)rac * D + i8 * 4;
        const float* xrb = x + (size_t)rbc * D + i8 * 4;
        float4 xa[4], xb[4];
        #pragma unroll
        for (int j = 0; j < 4; j++) xa[j] = *(const float4*)&xra[32 * j];
        #pragma unroll
        for (int j = 0; j < 4; j++) xb[j] = *(const float4*)&xrb[32 * j];

        float ea = xa[0].x * qv[0].x + xa[0].y * qv[0].y + xa[0].z * qv[0].z + xa[0].w * qv[0].w;
        float eb = xb[0].x * qv[0].x + xb[0].y * qv[0].y + xb[0].z * qv[0].z + xb[0].w * qv[0].w;
        #pragma unroll
        for (int j = 1; j < 4; j++) {
            ea += xa[j].x * qv[j].x + xa[j].y * qv[j].y + xa[j].z * qv[j].z + xa[j].w * qv[j].w;
            eb += xb[j].x * qv[j].x + xb[j].y * qv[j].y + xb[j].z * qv[j].z + xb[j].w * qv[j].w;
        }
        ea += __shfl_xor_sync(0xffffffffu, ea, 1);
        eb += __shfl_xor_sync(0xffffffffu, eb, 1);
        ea += __shfl_xor_sync(0xffffffffu, ea, 2);
        eb += __shfl_xor_sync(0xffffffffu, eb, 2);
        ea += __shfl_xor_sync(0xffffffffu, ea, 4);
        eb += __shfl_xor_sync(0xffffffffu, eb, 4);

        float eva = va ? ea : NEG_BIG;
        float evb = vb ? eb : NEG_BIG;
        float mn = fmaxf(m, fmaxf(eva, evb));
        float sc = ex2(m - mn);
        float pa = ex2(eva - mn);
        float pb = ex2(evb - mn);
        pa = va ? pa : 0.f;
        pb = vb ? pb : 0.f;
        s = s * sc + pa + pb;
        #pragma unroll
        for (int j = 0; j < 4; j++) {
            acc[j].x = acc[j].x * sc + pa * xa[j].x + pb * xb[j].x;
            acc[j].y = acc[j].y * sc + pa * xa[j].y + pb * xb[j].y;
            acc[j].z = acc[j].z * sc + pa * xa[j].z + pb * xb[j].z;
            acc[j].w = acc[j].w * sc + pa * xa[j].w + pb * xb[j].w;
        }
        m = mn;
    }

    #pragma unroll
    for (int ofs = 8; ofs <= 16; ofs <<= 1) {
        float m2 = __shfl_xor_sync(0xffffffffu, m, ofs);
        float s2 = __shfl_xor_sync(0xffffffffu, s, ofs);
        float M2 = fmaxf(m, m2);
        float fa = ex2(m - M2), fb = ex2(m2 - M2);
        s = s * fa + s2 * fb;
        #pragma unroll
        for (int j = 0; j < 4; j++) {
            float ox = __shfl_xor_sync(0xffffffffu, acc[j].x, ofs);
            float oy = __shfl_xor_sync(0xffffffffu, acc[j].y, ofs);
            float oz = __shfl_xor_sync(0xffffffffu, acc[j].z, ofs);
            float ow = __shfl_xor_sync(0xffffffffu, acc[j].w, ofs);
            acc[j].x = acc[j].x * fa + ox * fb;
            acc[j].y = acc[j].y * fa + oy * fb;
            acc[j].z = acc[j].z * fa + oz * fb;
            acc[j].w = acc[j].w * fa + ow * fb;
        }
        m = M2;
    }

    __shared__ float sm_m[4], sm_s[4];
    __shared__ float sm_acc[4][128];
    if (l < 8) {
        #pragma unroll
        for (int j = 0; j < 4; j++) *(float4*)&sm_acc[w][i8 * 4 + 32 * j] = acc[j];
        if (l == 0) { sm_m[w] = m; sm_s[w] = s; }
    }
    __syncthreads();

    float M = fmaxf(fmaxf(sm_m[0], sm_m[1]), fmaxf(sm_m[2], sm_m[3]));
    float stot = 0.f, racc = 0.f;
    #pragma unroll
    for (int ww = 0; ww < 4; ww++) {
        float fsc = ex2(sm_m[ww] - M);
        stot += fsc * sm_s[ww];
        racc += fsc * sm_acc[ww][t];
    }
    float r = racc / fmaxf(stot, 1e-16f);
    if (FINAL) {
        out[(size_t)g * 256 + 128 + t] = r;
        out[(size_t)g * 256 + t] = qrow[t];
    } else {
        g_r[(size_t)g * D + t] = r;
    }
}

// ---------- launch ----------
extern "C" void kernel_launch(void* const* d_in, const int* in_sizes, int n_in,
                              void* d_out, int out_size) {
    const float* x    = (const float*)d_in[0];
    const float* W_ih = (const float*)d_in[1];
    const float* W_hh = (const float*)d_in[2];
    const float* b_ih = (const float*)d_in[3];
    const float* b_hh = (const float*)d_in[4];
    const int*   idx  = (const int*)d_in[5];
    float* out = (float*)d_out;
    int N = in_sizes[5];
    (void)n_in; (void)out_size;

    cudaFuncSetAttribute(gemm_mma<false>, cudaFuncAttributeMaxDynamicSharedMemorySize,
                         GEMM_SMEM_BYTES);
    cudaFuncSetAttribute(gemm_mma<true>, cudaFuncAttributeMaxDynamicSharedMemorySize,
                         GEMM_SMEM_BYTES);

    // 1: setup (weight permute+split + bias + segment bounds)
    prep_all<<<512 + 17, 256>>>(W_ih, W_hh, b_ih, b_hh, idx, N);
    // 2: step-1 LSTM closed form + rank-1 gate base for step 2
    prep_state<<<1, 512>>>();
    // 3: step 1 attention (q = h1 broadcast) -> r1
    attn_kernel<true, false><<<G, 128>>>(x, out);
    // 4: step 2 gates = g1base + r1 @ W[128:256]
    gemm_mma<false><<<dim3(32, 4), 512, GEMM_SMEM_BYTES>>>();
    lstm_elem<true, true><<<(G * D + 255) / 256, 256>>>();
    // 5: step 2 attention -> r2
    attn_kernel<false, false><<<G, 128>>>(x, out);
    // 6: step 3 gates = bias + h2 @ W[0:128] + r2 @ W[128:256]
    gemm_mma<true><<<dim3(32, 4), 512, GEMM_SMEM_BYTES>>>();
    lstm_elem<false, false><<<(G * D + 255) / 256, 256>>>();
    // 7: step 3 attention -> q_star
    attn_kernel<false, true><<<G, 128>>>(x, out);
}

// round 15
// speedup vs baseline: 1.0603x; 1.0570x over previous
#include <cuda_runtime.h>
#include <math.h>
#include <stdint.h>

#define G 4096
#define D 128

#define NEG_BIG (-3.402823466e+38f)
#define LOG2E 1.44269504088896340736f

// ---------- static device scratch ----------
__device__ uint2 g_Wsp[256 * 512];   // combined weight, tf32 hi/lo split, [k][n'], n' = d*4+gate
__device__ float g_bias[512];        // permuted bias
__device__ float g_h[G * D];
__device__ float g_c[G * D];
__device__ float g_r[G * D];
__device__ float g_gates[G * 512];   // raw GEMM output (no bias), permuted n'
__device__ float g_h1[D];
__device__ float g_c1[D];
__device__ float g_g1base[512];      // permuted
__device__ int   g_segofs[G + 1];

__device__ __forceinline__ float sigf(float x) { return 1.f / (1.f + __expf(-x)); }

__device__ __forceinline__ float ex2(float x) {
    float r;
    asm("ex2.approx.ftz.f32 %0, %1;" : "=f"(r) : "f"(x));
    return r;
}

__device__ __forceinline__ uint32_t f2tf32(float v) {
    uint32_t r;
    asm("cvt.rna.tf32.f32 %0, %1;" : "=r"(r) : "f"(v));
    return r;
}

__device__ __forceinline__ void mma_tf32(float4& d, uint32_t a0, uint32_t a1, uint32_t a2,
                                         uint32_t a3, uint32_t b0, uint32_t b1) {
    asm volatile(
        "mma.sync.aligned.m16n8k8.row.col.f32.tf32.tf32.f32 "
        "{%0,%1,%2,%3}, {%4,%5,%6,%7}, {%8,%9}, {%0,%1,%2,%3};"
        : "+f"(d.x), "+f"(d.y), "+f"(d.z), "+f"(d.w)
        : "r"(a0), "r"(a1), "r"(a2), "r"(a3), "r"(b0), "r"(b1));
}

__device__ __forceinline__ uint2 split_tf32(float v) {
    uint32_t hi = f2tf32(v);
    float lo = v - __uint_as_float(hi);
    uint2 r; r.x = hi; r.y = f2tf32(lo);
    return r;
}

// ---------- setup: weight permute+split + bias + segment bounds, one launch ----------
__global__ void prep_all(const float* __restrict__ W_ih, const float* __restrict__ W_hh,
                         const float* __restrict__ b_ih, const float* __restrict__ b_hh,
                         const int* __restrict__ idx32, int N) {
    int bid = blockIdx.x;
    int t = threadIdx.x;
    if (bid < 512) {
        int idx = bid * 256 + t;
        int n = idx >> 8, k = idx & 255;
        int gate = n >> 7, d = n & 127;
        float w = W_ih[n * 256 + k];
        if (k < 128) w += W_hh[n * 128 + k];
        g_Wsp[k * 512 + d * 4 + gate] = split_tf32(w);
    } else {
        int gidx = (bid - 512) * 256 + t;
        if (gidx < 512) {
            int gate = gidx >> 7, d = gidx & 127;
            g_bias[d * 4 + gate] = b_ih[gidx] + b_hh[gidx];
        }
        if (gidx <= G) {
            int j = ((N - 1) & 1) ? (N - 1) : (N - 2);
            bool is64 = (idx32[j] == 0);
            const long long* idx64 = (const long long*)idx32;
            int lo = 0, hi = N;
            while (lo < hi) {
                int mid = (lo + hi) >> 1;
                long long v = is64 ? idx64[mid] : (long long)idx32[mid];
                if (v < (long long)gidx) lo = mid + 1; else hi = mid;
            }
            g_segofs[gidx] = lo;
        }
    }
}

// Fused: step-1 closed-form LSTM (state 0) + g1base (rank-1 part of step 2's gates).
__global__ void prep_state() {
    __shared__ float sh1[128];
    int t = threadIdx.x;
    if (t < 128) {
        float i = g_bias[t * 4 + 0], gg = g_bias[t * 4 + 2], o = g_bias[t * 4 + 3];
        float c = sigf(i) * tanhf(gg);
        float h = sigf(o) * tanhf(c);
        g_c1[t] = c;
        g_h1[t] = h;
        sh1[t] = h;
    }
    __syncthreads();
    float acc = g_bias[t];
    #pragma unroll 8
    for (int k = 0; k < 128; k++) {
        uint2 w = g_Wsp[k * 512 + t];
        acc += sh1[k] * (__uint_as_float(w.x) + __uint_as_float(w.y));
    }
    g_g1base[t] = acc;
}

// ---------- tensor-core GEMM (tf32 hi/lo split = fp32-accurate) ----------
// gates_raw[m][n'] = (HAS_A1 ? h@W[0:128] : 0) + r@W[128:256]  (bias added in attn cell)
// Block tile 128x128, grid (32,4)=128 blocks (one wave), 8 warps (warp tile 32x64),
// BK=32, single smem buffer + register prefetch. Fragments: m16n8k8 tf32, 3-mma split.
// (R11-proven config: 18.7us)
#define AS_STRIDE 36
#define BS_STRIDE 132
#define AS_ELEMS (128 * AS_STRIDE)
#define GEMM_SMEM_BYTES ((AS_ELEMS + 32 * BS_STRIDE) * 8)

template <bool HAS_A1>
__global__ void __launch_bounds__(256) gemm_mma() {
    extern __shared__ uint2 smem_dyn[];
    uint2* As = smem_dyn;                 // [m][k] m<128, k<32, stride 36
    uint2* Bs = smem_dyn + AS_ELEMS;      // [k][n] k<32, n<128, stride 132

    const int bx = blockIdx.x;            // m tile (0..31)
    const int by = blockIdx.y;            // n tile (0..3)
    const int t = threadIdx.x;
    const int wid = t >> 5, l = t & 31;
    const int wm = wid >> 1, wn = wid & 1;          // warp grid 4x2
    const int r = l >> 2, c = l & 3;

    const int m0 = bx * 128;
    const int n0 = by * 128;

    const int NCHUNK = HAS_A1 ? 8 : 4;
    const int KB0 = HAS_A1 ? 0 : 128;

    // staging thread coords
    const int a_row = t >> 3;             // + i*32
    const int a_kq = (t & 7) * 4;
    const int b_k = t >> 5;               // + i*8
    const int b_nq = (t & 31) * 4;

    float4 acc[2][8];
    #pragma unroll
    for (int mi = 0; mi < 2; mi++)
        #pragma unroll
        for (int ni = 0; ni < 8; ni++) acc[mi][ni] = make_float4(0.f, 0.f, 0.f, 0.f);

    float4 a_st[4];
    uint4 b_st[4][2];

    // load chunk 0
    {
        int kb = KB0;
        const float* A = (kb < 128) ? g_h : g_r;
        int kl = kb & 127;
        #pragma unroll
        for (int i = 0; i < 4; i++)
            a_st[i] = *(const float4*)&A[(size_t)(m0 + a_row + i * 32) * 128 + kl + a_kq];
        #pragma unroll
        for (int i = 0; i < 4; i++) {
            const uint2* src = &g_Wsp[(size_t)(kb + b_k + i * 8) * 512 + n0 + b_nq];
            b_st[i][0] = *(const uint4*)&src[0];
            b_st[i][1] = *(const uint4*)&src[2];
        }
    }
    #pragma unroll
    for (int i = 0; i < 4; i++) {
        uint2* d = &As[(a_row + i * 32) * AS_STRIDE + a_kq];
        d[0] = split_tf32(a_st[i].x); d[1] = split_tf32(a_st[i].y);
        d[2] = split_tf32(a_st[i].z); d[3] = split_tf32(a_st[i].w);
        uint2* e = &Bs[(b_k + i * 8) * BS_STRIDE + b_nq];
        *(uint4*)&e[0] = b_st[i][0];
        *(uint4*)&e[2] = b_st[i][1];
    }
    __syncthreads();

    for (int chunk = 0; chunk < NCHUNK; chunk++) {
        if (chunk + 1 < NCHUNK) {
            int kb = KB0 + (chunk + 1) * 32;
            const float* A = (kb < 128) ? g_h : g_r;
            int kl = kb & 127;
            #pragma unroll
            for (int i = 0; i < 4; i++)
                a_st[i] = *(const float4*)&A[(size_t)(m0 + a_row + i * 32) * 128 + kl + a_kq];
            #pragma unroll
            for (int i = 0; i < 4; i++) {
                const uint2* src = &g_Wsp[(size_t)(kb + b_k + i * 8) * 512 + n0 + b_nq];
                b_st[i][0] = *(const uint4*)&src[0];
                b_st[i][1] = *(const uint4*)&src[2];
            }
        }

        #pragma unroll
        for (int ks = 0; ks < 4; ks++) {
            int k0 = ks * 8;
            uint2 af[2][4];
            #pragma unroll
            for (int mi = 0; mi < 2; mi++) {
                int mb = wm * 32 + mi * 16;
                af[mi][0] = As[(mb + r) * AS_STRIDE + k0 + c];
                af[mi][1] = As[(mb + r + 8) * AS_STRIDE + k0 + c];
                af[mi][2] = As[(mb + r) * AS_STRIDE + k0 + c + 4];
                af[mi][3] = As[(mb + r + 8) * AS_STRIDE + k0 + c + 4];
            }
            uint2 bf[8][2];
            #pragma unroll
            for (int ni = 0; ni < 8; ni++) {
                int nb = wn * 64 + ni * 8;
                bf[ni][0] = Bs[(k0 + c) * BS_STRIDE + nb + r];
                bf[ni][1] = Bs[(k0 + c + 4) * BS_STRIDE + nb + r];
            }
            #pragma unroll
            for (int mi = 0; mi < 2; mi++) {
                #pragma unroll
                for (int ni = 0; ni < 8; ni++) {
                    // hi*hi
                    mma_tf32(acc[mi][ni], af[mi][0].x, af[mi][1].x, af[mi][2].x, af[mi][3].x,
                             bf[ni][0].x, bf[ni][1].x);
                    // hi*lo
                    mma_tf32(acc[mi][ni], af[mi][0].x, af[mi][1].x, af[mi][2].x, af[mi][3].x,
                             bf[ni][0].y, bf[ni][1].y);
                    // lo*hi
                    mma_tf32(acc[mi][ni], af[mi][0].y, af[mi][1].y, af[mi][2].y, af[mi][3].y,
                             bf[ni][0].x, bf[ni][1].x);
                }
            }
        }
        __syncthreads();
        if (chunk + 1 < NCHUNK) {
            #pragma unroll
            for (int i = 0; i < 4; i++) {
                uint2* d = &As[(a_row + i * 32) * AS_STRIDE + a_kq];
                d[0] = split_tf32(a_st[i].x); d[1] = split_tf32(a_st[i].y);
                d[2] = split_tf32(a_st[i].z); d[3] = split_tf32(a_st[i].w);
                uint2* e = &Bs[(b_k + i * 8) * BS_STRIDE + b_nq];
                *(uint4*)&e[0] = b_st[i][0];
                *(uint4*)&e[2] = b_st[i][1];
            }
            __syncthreads();
        }
    }

    // store raw gates
    #pragma unroll
    for (int mi = 0; mi < 2; mi++) {
        int mg = m0 + wm * 32 + mi * 16 + r;
        #pragma unroll
        for (int ni = 0; ni < 8; ni++) {
            int np = n0 + wn * 64 + ni * 8 + 2 * c;
            float2 loa; loa.x = acc[mi][ni].x; loa.y = acc[mi][ni].y;
            float2 hib; hib.x = acc[mi][ni].z; hib.y = acc[mi][ni].w;
            *(float2*)&g_gates[(size_t)mg * 512 + np] = loa;
            *(float2*)&g_gates[(size_t)(mg + 8) * 512 + np] = hib;
        }
    }
}

// ---------- attention with fused LSTM cell prologue ----------
// CELL=0: q = g_h1 (step 1, broadcast).
// CELL=1: cell from g_gates + g_g1base, c_old=g_c1[d]; writes g_c, g_h; q = h (step 2).
// CELL=2: cell from g_gates + g_bias, c_old=g_c[g]; writes nothing; q = h (step 3, FINAL).
template <int CELL, bool FINAL>
__global__ void __launch_bounds__(128) attn_kernel(const float* __restrict__ x,
                                                   float* __restrict__ out) {
    int g = blockIdx.x;
    int start = g_segofs[g], end = g_segofs[g + 1];
    int t = threadIdx.x, w = t >> 5, l = t & 31;
    int i8 = l & 7, grp = l >> 3;

    __shared__ float sq[128];
    if (CELL > 0) {
        float4 gv = *(const float4*)&g_gates[(size_t)g * 512 + t * 4];
        const float* base = (CELL == 1) ? g_g1base : g_bias;
        float4 bz = *(const float4*)&base[t * 4];
        float gi = gv.x + bz.x, gf = gv.y + bz.y, gg = gv.z + bz.z, go = gv.w + bz.w;
        float cold = (CELL == 1) ? g_c1[t] : g_c[(size_t)g * 128 + t];
        float cn = sigf(gf) * cold + sigf(gi) * tanhf(gg);
        float h = sigf(go) * tanhf(cn);
        if (CELL == 1) {
            g_c[(size_t)g * 128 + t] = cn;
            g_h[(size_t)g * 128 + t] = h;
        }
        sq[t] = h;
        __syncthreads();
    }
    const float* qrow = (CELL == 0) ? g_h1 : sq;

    float4 qv[4];
    #pragma unroll
    for (int j = 0; j < 4; j++) {
        float4 q = *(const float4*)&qrow[i8 * 4 + 32 * j];
        qv[j].x = q.x * LOG2E; qv[j].y = q.y * LOG2E;
        qv[j].z = q.z * LOG2E; qv[j].w = q.w * LOG2E;
    }

    float m = NEG_BIG, s = 0.f;
    float4 acc[4] = {};

    for (int r0 = start + w * 8; r0 < end; r0 += 32) {
        int ra = r0 + grp, rb = r0 + 4 + grp;
        bool va = ra < end, vb = rb < end;
        int rac = va ? ra : end - 1;
        int rbc = vb ? rb : end - 1;
        const float* xra = x + (size_t)rac * D + i8 * 4;
        const float* xrb = x + (size_t)rbc * D + i8 * 4;
        float4 xa[4], xb[4];
        #pragma unroll
        for (int j = 0; j < 4; j++) xa[j] = *(const float4*)&xra[32 * j];
        #pragma unroll
        for (int j = 0; j < 4; j++) xb[j] = *(const float4*)&xrb[32 * j];

        float ea = xa[0].x * qv[0].x + xa[0].y * qv[0].y + xa[0].z * qv[0].z + xa[0].w * qv[0].w;
        float eb = xb[0].x * qv[0].x + xb[0].y * qv[0].y + xb[0].z * qv[0].z + xb[0].w * qv[0].w;
        #pragma unroll
        for (int j = 1; j < 4; j++) {
            ea += xa[j].x * qv[j].x + xa[j].y * qv[j].y + xa[j].z * qv[j].z + xa[j].w * qv[j].w;
            eb += xb[j].x * qv[j].x + xb[j].y * qv[j].y + xb[j].z * qv[j].z + xb[j].w * qv[j].w;
        }
        ea += __shfl_xor_sync(0xffffffffu, ea, 1);
        eb += __shfl_xor_sync(0xffffffffu, eb, 1);
        ea += __shfl_xor_sync(0xffffffffu, ea, 2);
        eb += __shfl_xor_sync(0xffffffffu, eb, 2);
        ea += __shfl_xor_sync(0xffffffffu, ea, 4);
        eb += __shfl_xor_sync(0xffffffffu, eb, 4);

        float eva = va ? ea : NEG_BIG;
        float evb = vb ? eb : NEG_BIG;
        float mn = fmaxf(m, fmaxf(eva, evb));
        float sc = ex2(m - mn);
        float pa = ex2(eva - mn);
        float pb = ex2(evb - mn);
        pa = va ? pa : 0.f;
        pb = vb ? pb : 0.f;
        s = s * sc + pa + pb;
        #pragma unroll
        for (int j = 0; j < 4; j++) {
            acc[j].x = acc[j].x * sc + pa * xa[j].x + pb * xb[j].x;
            acc[j].y = acc[j].y * sc + pa * xa[j].y + pb * xb[j].y;
            acc[j].z = acc[j].z * sc + pa * xa[j].z + pb * xb[j].z;
            acc[j].w = acc[j].w * sc + pa * xa[j].w + pb * xb[j].w;
        }
        m = mn;
    }

    #pragma unroll
    for (int ofs = 8; ofs <= 16; ofs <<= 1) {
        float m2 = __shfl_xor_sync(0xffffffffu, m, ofs);
        float s2 = __shfl_xor_sync(0xffffffffu, s, ofs);
        float M2 = fmaxf(m, m2);
        float fa = ex2(m - M2), fb = ex2(m2 - M2);
        s = s * fa + s2 * fb;
        #pragma unroll
        for (int j = 0; j < 4; j++) {
            float ox = __shfl_xor_sync(0xffffffffu, acc[j].x, ofs);
            float oy = __shfl_xor_sync(0xffffffffu, acc[j].y, ofs);
            float oz = __shfl_xor_sync(0xffffffffu, acc[j].z, ofs);
            float ow = __shfl_xor_sync(0xffffffffu, acc[j].w, ofs);
            acc[j].x = acc[j].x * fa + ox * fb;
            acc[j].y = acc[j].y * fa + oy * fb;
            acc[j].z = acc[j].z * fa + oz * fb;
            acc[j].w = acc[j].w * fa + ow * fb;
        }
        m = M2;
    }

    __shared__ float sm_m[4], sm_s[4];
    __shared__ float sm_acc[4][128];
    if (l < 8) {
        #pragma unroll
        for (int j = 0; j < 4; j++) *(float4*)&sm_acc[w][i8 * 4 + 32 * j] = acc[j];
        if (l == 0) { sm_m[w] = m; sm_s[w] = s; }
    }
    __syncthreads();

    float M = fmaxf(fmaxf(sm_m[0], sm_m[1]), fmaxf(sm_m[2], sm_m[3]));
    float stot = 0.f, racc = 0.f;
    #pragma unroll
    for (int ww = 0; ww < 4; ww++) {
        float fsc = ex2(sm_m[ww] - M);
        stot += fsc * sm_s[ww];
        racc += fsc * sm_acc[ww][t];
    }
    float r = racc / fmaxf(stot, 1e-16f);
    if (FINAL) {
        out[(size_t)g * 256 + 128 + t] = r;
        out[(size_t)g * 256 + t] = qrow[t];
    } else {
        g_r[(size_t)g * D + t] = r;
    }
}

// ---------- launch ----------
extern "C" void kernel_launch(void* const* d_in, const int* in_sizes, int n_in,
                              void* d_out, int out_size) {
    const float* x    = (const float*)d_in[0];
    const float* W_ih = (const float*)d_in[1];
    const float* W_hh = (const float*)d_in[2];
    const float* b_ih = (const float*)d_in[3];
    const float* b_hh = (const float*)d_in[4];
    const int*   idx  = (const int*)d_in[5];
    float* out = (float*)d_out;
    int N = in_sizes[5];
    (void)n_in; (void)out_size;

    cudaFuncSetAttribute(gemm_mma<false>, cudaFuncAttributeMaxDynamicSharedMemorySize,
                         GEMM_SMEM_BYTES);
    cudaFuncSetAttribute(gemm_mma<true>, cudaFuncAttributeMaxDynamicSharedMemorySize,
                         GEMM_SMEM_BYTES);

    // 1: setup (weight permute+split + bias + segment bounds)
    prep_all<<<512 + 17, 256>>>(W_ih, W_hh, b_ih, b_hh, idx, N);
    // 2: step-1 LSTM closed form + rank-1 gate base for step 2
    prep_state<<<1, 512>>>();
    // 3: step 1 attention (q = h1 broadcast) -> r1
    attn_kernel<0, false><<<G, 128>>>(x, out);
    // 4: step 2 gates_raw = r1 @ W[128:256]
    gemm_mma<false><<<dim3(32, 4), 256, GEMM_SMEM_BYTES>>>();
    // 5: step 2 attention (fused cell -> h2,c2; q=h2) -> r2
    attn_kernel<1, false><<<G, 128>>>(x, out);
    // 6: step 3 gates_raw = h2 @ W[0:128] + r2 @ W[128:256]
    gemm_mma<true><<<dim3(32, 4), 256, GEMM_SMEM_BYTES>>>();
    // 7: step 3 attention (fused cell; q=h3) -> q_star
    attn_kernel<2, true><<<G, 128>>>(x, out);
}